// round 6
// baseline (speedup 1.0000x reference)
#include <cuda_runtime.h>
#include <cuda_fp16.h>
#include <cstdint>

#define N_NODES 100000
#define N_EDGES 600000
#define HIDDEN  128
#define ALPHA   0.1f
#define KHOPS   10
#define EDGE_CAP 1400000   // 600k edges + <=7 pad per node

// ---------------- device scratch (static; no allocation) ----------------
__device__ __half g_Wh  [HIDDEN * HIDDEN];            // fp16 W
__device__ __half g_h0h [(size_t)N_NODES * HIDDEN];
__device__ __half g_bufA[(size_t)N_NODES * HIDDEN];
__device__ __half g_bufB[(size_t)N_NODES * HIDDEN];
__device__ int    g_cnt    [N_NODES];
__device__ int    g_rowptr [N_NODES + 1];
__device__ int    g_cursor [N_NODES];
__device__ float  g_dinv   [N_NODES];
__device__ float  g_selfw  [N_NODES];   // (1-alpha) * dinv^2
__device__ int2   g_edge   [EDGE_CAP];  // CSR by dst: {src, weight bits}; pads {0,0}
__device__ int    g_is64;               // 1 if edge_index is int64, 0 if int32

// ---------------- fp16 vector helpers ----------------
__device__ __forceinline__ void sth4(__half* p, float4 v) {
    __half2 a = __floats2half2_rn(v.x, v.y);
    __half2 b = __floats2half2_rn(v.z, v.w);
    uint2 raw;
    raw.x = *(unsigned*)&a;
    raw.y = *(unsigned*)&b;
    *(uint2*)p = raw;
}
__device__ __forceinline__ void ldh8(const __half* p, float4& lo, float4& hi) {
    uint4 raw = *(const uint4*)p;
    float2 f0 = __half22float2(*(__half2*)&raw.x);
    float2 f1 = __half22float2(*(__half2*)&raw.y);
    float2 f2 = __half22float2(*(__half2*)&raw.z);
    float2 f3 = __half22float2(*(__half2*)&raw.w);
    lo = make_float4(f0.x, f0.y, f1.x, f1.y);
    hi = make_float4(f2.x, f2.y, f3.x, f3.y);
}
__device__ __forceinline__ void fma8(float4& aL, float4& aH, float w, float4 vL, float4 vH) {
    aL.x += w * vL.x; aL.y += w * vL.y; aL.z += w * vL.z; aL.w += w * vL.w;
    aH.x += w * vH.x; aH.y += w * vH.y; aH.z += w * vH.z; aH.w += w * vH.w;
}
__device__ __forceinline__ unsigned f2h2(float a, float b) {
    __half2 h = __floats2half2_rn(a, b);
    return *(unsigned*)&h;
}

// ---------------- launch 0: zero cnt + zero edge slab + convert W + probe ----------------
__global__ void probe_zero(const int* __restrict__ ei32, const float* __restrict__ W,
                           int* __restrict__ cnt, int2* __restrict__ edge,
                           __half* __restrict__ Wh) {
    int i = blockIdx.x * 256 + threadIdx.x;   // 100,096 threads
    if (i < N_NODES) cnt[i] = 0;
    for (int j = i; j < EDGE_CAP; j += 391 * 256) edge[j] = make_int2(0, 0);
    if (i < HIDDEN * HIDDEN / 4) {
        float4 v = ((const float4*)W)[i];
        sth4(Wh + (size_t)i * 4, v);
    }
    if (i == 0) {
        int acc = 0;
        for (int k = 0; k < 128; k++) acc |= ei32[2 * k + 1];
        g_is64 = (acc == 0) ? 1 : 0;
    }
}

__device__ __forceinline__ int load_idx(const int* ei32, long long pos, int is64) {
    return is64 ? ei32[2 * pos] : ei32[pos];
}

// ---------------- launch 1: in-degree count ----------------
__global__ void deg_count(const int* __restrict__ ei32, int* __restrict__ cnt) {
    int e = blockIdx.x * 256 + threadIdx.x;
    if (e < N_EDGES) {
        int d = load_idx(ei32, (long long)N_EDGES + e, g_is64);
        if ((unsigned)d < N_NODES) atomicAdd(&cnt[d], 1);
    }
}

// ---------------- launch 2: tensor-core GEMM h0 = x @ W^T + b ----------------
// x fp32 (converted inline), W fp16 smem, fp32 accum, fp16 out.
#define WSTRIDE 136
__global__ __launch_bounds__(256) void gemm_hmma(
    const float* __restrict__ x, const __half* __restrict__ Wh,
    const float* __restrict__ b, __half* __restrict__ out)
{
    __shared__ __half Ws[128 * WSTRIDE];
    __shared__ float bs[128];
    const int tid = threadIdx.x;

#pragma unroll
    for (int it = 0; it < 8; it++) {
        int idx = it * 256 + tid;            // uint4 index over [128 rows][16 uint4]
        int r = idx >> 4, c = (idx & 15) * 8;
        *(uint4*)&Ws[r * WSTRIDE + c] = ((const uint4*)Wh)[idx];
    }
    if (tid < 128) bs[tid] = b[tid];
    __syncthreads();

    const int w = tid >> 5, lane = tid & 31;
    const int r  = lane >> 2;        // 0..7
    const int kq = (lane & 3) * 2;   // 0,2,4,6
    const int Rbase = blockIdx.x * 128 + w * 16;

    int row0 = Rbase + r;
    int row1 = Rbase + r + 8;
    int row0c = row0 < N_NODES ? row0 : 0;
    int row1c = row1 < N_NODES ? row1 : 0;

    float d[16][4];
#pragma unroll
    for (int nt = 0; nt < 16; nt++)
#pragma unroll
        for (int q = 0; q < 4; q++) d[nt][q] = 0.0f;

    const float* a0p = x + (size_t)row0c * HIDDEN;
    const float* a1p = x + (size_t)row1c * HIDDEN;

#pragma unroll
    for (int ks = 0; ks < 8; ks++) {
        int k0 = ks * 16 + kq;
        float2 f0 = *(const float2*)(a0p + k0);
        float2 f1 = *(const float2*)(a1p + k0);
        float2 f2 = *(const float2*)(a0p + k0 + 8);
        float2 f3 = *(const float2*)(a1p + k0 + 8);
        unsigned a0 = f2h2(f0.x, f0.y);
        unsigned a1 = f2h2(f1.x, f1.y);
        unsigned a2 = f2h2(f2.x, f2.y);
        unsigned a3 = f2h2(f3.x, f3.y);
#pragma unroll
        for (int nt = 0; nt < 16; nt++) {
            int c = nt * 8 + r;
            unsigned b0 = *(const unsigned*)&Ws[c * WSTRIDE + ks * 16 + kq];
            unsigned b1 = *(const unsigned*)&Ws[c * WSTRIDE + ks * 16 + kq + 8];
            asm volatile(
                "mma.sync.aligned.m16n8k16.row.col.f32.f16.f16.f32 "
                "{%0,%1,%2,%3}, {%4,%5,%6,%7}, {%8,%9}, {%0,%1,%2,%3};"
                : "+f"(d[nt][0]), "+f"(d[nt][1]), "+f"(d[nt][2]), "+f"(d[nt][3])
                : "r"(a0), "r"(a1), "r"(a2), "r"(a3), "r"(b0), "r"(b1));
        }
    }

    const int c0 = (lane & 3) * 2;
#pragma unroll
    for (int nt = 0; nt < 16; nt++) {
        int col = nt * 8 + c0;
        if (row0 < N_NODES) {
            __half2 v = __floats2half2_rn(d[nt][0] + bs[col], d[nt][1] + bs[col + 1]);
            *(__half2*)&out[(size_t)row0 * HIDDEN + col] = v;
        }
        if (row1 < N_NODES) {
            __half2 v = __floats2half2_rn(d[nt][2] + bs[col], d[nt][3] + bs[col + 1]);
            *(__half2*)&out[(size_t)row1 * HIDDEN + col] = v;
        }
    }
}

// ---------------- launch 3: exclusive scan (padded to 8) + node norm prep ----------------
__global__ __launch_bounds__(1024) void scan_prep(
    const int* __restrict__ cnt, int* __restrict__ row_ptr, int* __restrict__ cursor,
    float* __restrict__ dinv, float* __restrict__ selfw)
{
    const int PER = (N_NODES + 1023) / 1024;   // 98
    int t = threadIdx.x;
    int start = t * PER;
    int local = 0;
    for (int k = 0; k < PER; k++) {
        int i = start + k;
        if (i < N_NODES) local += (cnt[i] + 7) & ~7;   // padded to 8
    }
    __shared__ int sh[1024];
    sh[t] = local;
    __syncthreads();
    for (int d = 1; d < 1024; d <<= 1) {
        int v = (t >= d) ? sh[t - d] : 0;
        __syncthreads();
        sh[t] += v;
        __syncthreads();
    }
    int run = sh[t] - local;
    for (int k = 0; k < PER; k++) {
        int i = start + k;
        if (i < N_NODES) {
            row_ptr[i] = run;
            cursor[i]  = run;
            run += (cnt[i] + 7) & ~7;
            float r = rsqrtf((float)cnt[i] + 1.0f);   // +1 self-loop (real degree)
            dinv[i]  = r;
            selfw[i] = (1.0f - ALPHA) * r * r;
        }
    }
    if (t == 1023) row_ptr[N_NODES] = sh[1023];
}

// ---------------- launch 4: CSR edge placement ----------------
__global__ void edge_place(const int* __restrict__ ei32, const float* __restrict__ dinv,
                           int* __restrict__ cursor, int2* __restrict__ edge)
{
    int e = blockIdx.x * 256 + threadIdx.x;
    if (e < N_EDGES) {
        int is64 = g_is64;
        int s = load_idx(ei32, e, is64);
        int d = load_idx(ei32, (long long)N_EDGES + e, is64);
        if ((unsigned)s >= N_NODES) s = 0;
        if ((unsigned)d >= N_NODES) d = 0;
        int pos = atomicAdd(&cursor[d], 1);
        float w = (1.0f - ALPHA) * dinv[s] * dinv[d];
        edge[pos] = make_int2(s, __float_as_int(w));
    }
}

// ---------------- per-hop fused pull: 16 lanes per node, 8 edges/iter ----------------
// out[n] = alpha*h0[n] + selfw[n]*cur[n] + sum_e w_e * cur[src_e]
// edge lists padded to multiple of 8 with {src=0, w=0}.
template <bool FINAL>
__global__ __launch_bounds__(256) void prop_kernel(
    const __half* __restrict__ cur, const __half* __restrict__ h0,
    const float* __restrict__ selfw,
    const int* __restrict__ row_ptr, const int2* __restrict__ edge,
    void* __restrict__ outp)
{
    int gtid = blockIdx.x * 256 + threadIdx.x;
    int n = gtid >> 4;          // 16 lanes per node
    int l = gtid & 15;
    if (n >= N_NODES) return;

    const size_t off = (size_t)n * HIDDEN + l * 8;
    float4 h0L, h0H, svL, svH;
    ldh8(h0 + off, h0L, h0H);
    ldh8(cur + off, svL, svH);
    float sw = selfw[n];

    float4 aL, aH;
    aL.x = ALPHA * h0L.x + sw * svL.x;  aL.y = ALPHA * h0L.y + sw * svL.y;
    aL.z = ALPHA * h0L.z + sw * svL.z;  aL.w = ALPHA * h0L.w + sw * svL.w;
    aH.x = ALPHA * h0H.x + sw * svH.x;  aH.y = ALPHA * h0H.y + sw * svH.y;
    aH.z = ALPHA * h0H.z + sw * svH.z;  aH.w = ALPHA * h0H.w + sw * svH.w;

    int beg = __ldg(row_ptr + n);
    int end = __ldg(row_ptr + n + 1);
    for (int j = beg; j < end; j += 8) {
        const int4* ep = (const int4*)(edge + j);   // 8 edges = 4 int4
        int4 E0 = __ldg(ep);
        int4 E1 = __ldg(ep + 1);
        int4 E2 = __ldg(ep + 2);
        int4 E3 = __ldg(ep + 3);
        float4 v0L,v0H,v1L,v1H,v2L,v2H,v3L,v3H,v4L,v4H,v5L,v5H,v6L,v6H,v7L,v7H;
        ldh8(cur + (size_t)E0.x * HIDDEN + l * 8, v0L, v0H);
        ldh8(cur + (size_t)E0.z * HIDDEN + l * 8, v1L, v1H);
        ldh8(cur + (size_t)E1.x * HIDDEN + l * 8, v2L, v2H);
        ldh8(cur + (size_t)E1.z * HIDDEN + l * 8, v3L, v3H);
        ldh8(cur + (size_t)E2.x * HIDDEN + l * 8, v4L, v4H);
        ldh8(cur + (size_t)E2.z * HIDDEN + l * 8, v5L, v5H);
        ldh8(cur + (size_t)E3.x * HIDDEN + l * 8, v6L, v6H);
        ldh8(cur + (size_t)E3.z * HIDDEN + l * 8, v7L, v7H);
        fma8(aL, aH, __int_as_float(E0.y), v0L, v0H);
        fma8(aL, aH, __int_as_float(E0.w), v1L, v1H);
        fma8(aL, aH, __int_as_float(E1.y), v2L, v2H);
        fma8(aL, aH, __int_as_float(E1.w), v3L, v3H);
        fma8(aL, aH, __int_as_float(E2.y), v4L, v4H);
        fma8(aL, aH, __int_as_float(E2.w), v5L, v5H);
        fma8(aL, aH, __int_as_float(E3.y), v6L, v6H);
        fma8(aL, aH, __int_as_float(E3.w), v7L, v7H);
    }

    if (FINAL) {
        float* o = (float*)outp + off;
        *(float4*)o       = aL;
        *(float4*)(o + 4) = aH;
    } else {
        __half* o = (__half*)outp + off;
        sth4(o, aL);
        sth4(o + 4, aH);
    }
}

// ---------------- launch ----------------
extern "C" void kernel_launch(void* const* d_in, const int* in_sizes, int n_in,
                              void* d_out, int out_size)
{
    const float* x    = (const float*)d_in[0];
    const int*   ei32 = (const int*)d_in[1];    // int32 OR int64 (device probe)
    const float* W    = (const float*)d_in[2];
    const float* b    = (const float*)d_in[3];
    float* out = (float*)d_out;

    __half *Wh, *h0h, *bufA, *bufB;
    float *dinv, *selfw;
    int *cnt, *row_ptr, *cursor;
    int2 *edge;
    cudaGetSymbolAddress((void**)&Wh,      g_Wh);
    cudaGetSymbolAddress((void**)&h0h,     g_h0h);
    cudaGetSymbolAddress((void**)&bufA,    g_bufA);
    cudaGetSymbolAddress((void**)&bufB,    g_bufB);
    cudaGetSymbolAddress((void**)&cnt,     g_cnt);
    cudaGetSymbolAddress((void**)&row_ptr, g_rowptr);
    cudaGetSymbolAddress((void**)&cursor,  g_cursor);
    cudaGetSymbolAddress((void**)&dinv,    g_dinv);
    cudaGetSymbolAddress((void**)&selfw,   g_selfw);
    cudaGetSymbolAddress((void**)&edge,    g_edge);

    const int NB_N = (N_NODES + 255) / 256;   // 391
    const int NB_E = (N_EDGES + 255) / 256;   // 2344
    const int NB_G = (N_NODES + 127) / 128;   // 782

    probe_zero<<<NB_N, 256>>>(ei32, W, cnt, edge, Wh);            // 0
    deg_count <<<NB_E, 256>>>(ei32, cnt);                         // 1
    gemm_hmma <<<NB_G, 256>>>(x, Wh, b, h0h);                     // 2
    scan_prep <<<1, 1024>>>(cnt, row_ptr, cursor, dinv, selfw);   // 3
    edge_place<<<NB_E, 256>>>(ei32, dinv, cursor, edge);          // 4

    const int NB_PROP = (N_NODES * 16 + 255) / 256;   // 6250
    const __half* cur = h0h;
    for (int hop = 0; hop < KHOPS; hop++) {           // first prop = index 5 (profiled)
        if (hop == KHOPS - 1) {
            prop_kernel<true><<<NB_PROP, 256>>>(cur, h0h, selfw, row_ptr, edge, out);
        } else {
            __half* nxt = (hop & 1) ? bufB : bufA;
            prop_kernel<false><<<NB_PROP, 256>>>(cur, h0h, selfw, row_ptr, edge, nxt);
            cur = nxt;
        }
    }
}

// round 7
// speedup vs baseline: 1.7749x; 1.7749x over previous
#include <cuda_runtime.h>
#include <cuda_fp16.h>
#include <cstdint>

#define N_NODES 100000
#define N_EDGES 600000
#define HIDDEN  128
#define ALPHA   0.1f
#define KHOPS   10
#define EDGE_CAP 1000000   // 600k edges + <=3 pad per node

// ---------------- device scratch (static; no allocation) ----------------
__device__ __half g_Wh  [HIDDEN * HIDDEN];            // fp16 W
__device__ __half g_h0h [(size_t)N_NODES * HIDDEN];
__device__ __half g_bufA[(size_t)N_NODES * HIDDEN];
__device__ __half g_bufB[(size_t)N_NODES * HIDDEN];
__device__ int    g_cnt    [N_NODES];
__device__ int    g_rowbeg [N_NODES];
__device__ int    g_cursor [N_NODES];
__device__ float  g_dinv   [N_NODES];
__device__ float  g_selfw  [N_NODES];   // (1-alpha) * dinv^2
__device__ int2   g_edge   [EDGE_CAP];  // CSR by dst: {src, weight bits}; pads {0,0}
__device__ int    g_total;              // running allocator for edge ranges
__device__ int    g_is64;               // 1 if edge_index is int64, 0 if int32

// ---------------- fp16 vector helpers ----------------
__device__ __forceinline__ void sth4(__half* p, float4 v) {
    __half2 a = __floats2half2_rn(v.x, v.y);
    __half2 b = __floats2half2_rn(v.z, v.w);
    uint2 raw;
    raw.x = *(unsigned*)&a;
    raw.y = *(unsigned*)&b;
    *(uint2*)p = raw;
}
__device__ __forceinline__ void ldh8(const __half* p, float4& lo, float4& hi) {
    uint4 raw = *(const uint4*)p;
    float2 f0 = __half22float2(*(__half2*)&raw.x);
    float2 f1 = __half22float2(*(__half2*)&raw.y);
    float2 f2 = __half22float2(*(__half2*)&raw.z);
    float2 f3 = __half22float2(*(__half2*)&raw.w);
    lo = make_float4(f0.x, f0.y, f1.x, f1.y);
    hi = make_float4(f2.x, f2.y, f3.x, f3.y);
}
__device__ __forceinline__ void fma8(float4& aL, float4& aH, float w, float4 vL, float4 vH) {
    aL.x += w * vL.x; aL.y += w * vL.y; aL.z += w * vL.z; aL.w += w * vL.w;
    aH.x += w * vH.x; aH.y += w * vH.y; aH.z += w * vH.z; aH.w += w * vH.w;
}
__device__ __forceinline__ unsigned f2h2(float a, float b) {
    __half2 h = __floats2half2_rn(a, b);
    return *(unsigned*)&h;
}

// ---------------- launch 0: zero cnt + edge slab + convert W + probe ----------------
__global__ void probe_zero(const int* __restrict__ ei32, const float* __restrict__ W,
                           int* __restrict__ cnt, int2* __restrict__ edge,
                           __half* __restrict__ Wh) {
    int i = blockIdx.x * 256 + threadIdx.x;   // 100,096 threads
    if (i < N_NODES) cnt[i] = 0;
    for (int j = i; j < EDGE_CAP; j += 391 * 256) edge[j] = make_int2(0, 0);
    if (i < HIDDEN * HIDDEN / 4) {
        float4 v = ((const float4*)W)[i];
        sth4(Wh + (size_t)i * 4, v);
    }
    if (i == 0) {
        g_total = 0;
        int acc = 0;
        for (int k = 0; k < 128; k++) acc |= ei32[2 * k + 1];
        g_is64 = (acc == 0) ? 1 : 0;
    }
}

__device__ __forceinline__ int load_idx(const int* ei32, long long pos, int is64) {
    return is64 ? ei32[2 * pos] : ei32[pos];
}

// ---------------- launch 1: in-degree count ----------------
__global__ void deg_count(const int* __restrict__ ei32, int* __restrict__ cnt) {
    int e = blockIdx.x * 256 + threadIdx.x;
    if (e < N_EDGES) {
        int d = load_idx(ei32, (long long)N_EDGES + e, g_is64);
        if ((unsigned)d < N_NODES) atomicAdd(&cnt[d], 1);
    }
}

// ---------------- launch 2: tensor-core GEMM h0 = x @ W^T + b ----------------
#define WSTRIDE 136
__global__ __launch_bounds__(256) void gemm_hmma(
    const float* __restrict__ x, const __half* __restrict__ Wh,
    const float* __restrict__ b, __half* __restrict__ out)
{
    __shared__ __half Ws[128 * WSTRIDE];
    __shared__ float bs[128];
    const int tid = threadIdx.x;

#pragma unroll
    for (int it = 0; it < 8; it++) {
        int idx = it * 256 + tid;            // uint4 index over [128 rows][16 uint4]
        int r = idx >> 4, c = (idx & 15) * 8;
        *(uint4*)&Ws[r * WSTRIDE + c] = ((const uint4*)Wh)[idx];
    }
    if (tid < 128) bs[tid] = b[tid];
    __syncthreads();

    const int w = tid >> 5, lane = tid & 31;
    const int r  = lane >> 2;        // 0..7
    const int kq = (lane & 3) * 2;   // 0,2,4,6
    const int Rbase = blockIdx.x * 128 + w * 16;

    int row0 = Rbase + r;
    int row1 = Rbase + r + 8;
    int row0c = row0 < N_NODES ? row0 : 0;
    int row1c = row1 < N_NODES ? row1 : 0;

    float d[16][4];
#pragma unroll
    for (int nt = 0; nt < 16; nt++)
#pragma unroll
        for (int q = 0; q < 4; q++) d[nt][q] = 0.0f;

    const float* a0p = x + (size_t)row0c * HIDDEN;
    const float* a1p = x + (size_t)row1c * HIDDEN;

#pragma unroll
    for (int ks = 0; ks < 8; ks++) {
        int k0 = ks * 16 + kq;
        float2 f0 = *(const float2*)(a0p + k0);
        float2 f1 = *(const float2*)(a1p + k0);
        float2 f2 = *(const float2*)(a0p + k0 + 8);
        float2 f3 = *(const float2*)(a1p + k0 + 8);
        unsigned a0 = f2h2(f0.x, f0.y);
        unsigned a1 = f2h2(f1.x, f1.y);
        unsigned a2 = f2h2(f2.x, f2.y);
        unsigned a3 = f2h2(f3.x, f3.y);
#pragma unroll
        for (int nt = 0; nt < 16; nt++) {
            int c = nt * 8 + r;
            unsigned b0 = *(const unsigned*)&Ws[c * WSTRIDE + ks * 16 + kq];
            unsigned b1 = *(const unsigned*)&Ws[c * WSTRIDE + ks * 16 + kq + 8];
            asm volatile(
                "mma.sync.aligned.m16n8k16.row.col.f32.f16.f16.f32 "
                "{%0,%1,%2,%3}, {%4,%5,%6,%7}, {%8,%9}, {%0,%1,%2,%3};"
                : "+f"(d[nt][0]), "+f"(d[nt][1]), "+f"(d[nt][2]), "+f"(d[nt][3])
                : "r"(a0), "r"(a1), "r"(a2), "r"(a3), "r"(b0), "r"(b1));
        }
    }

    const int c0 = (lane & 3) * 2;
#pragma unroll
    for (int nt = 0; nt < 16; nt++) {
        int col = nt * 8 + c0;
        if (row0 < N_NODES) {
            __half2 v = __floats2half2_rn(d[nt][0] + bs[col], d[nt][1] + bs[col + 1]);
            *(__half2*)&out[(size_t)row0 * HIDDEN + col] = v;
        }
        if (row1 < N_NODES) {
            __half2 v = __floats2half2_rn(d[nt][2] + bs[col], d[nt][3] + bs[col + 1]);
            *(__half2*)&out[(size_t)row1 * HIDDEN + col] = v;
        }
    }
}

// ---------------- launch 3: parallel range allocation + node norm prep ----------------
// CSR row order is irrelevant; each node just needs a contiguous slab.
__global__ void alloc_prep(const int* __restrict__ cnt,
                           int* __restrict__ rowbeg, int* __restrict__ cursor,
                           float* __restrict__ dinv, float* __restrict__ selfw)
{
    int i = blockIdx.x * 256 + threadIdx.x;
    if (i < N_NODES) {
        int c = cnt[i];
        int pad = (c + 3) & ~3;
        int base = atomicAdd(&g_total, pad);
        rowbeg[i] = base;
        cursor[i] = base;
        float r = rsqrtf((float)c + 1.0f);   // +1 self-loop (real degree)
        dinv[i]  = r;
        selfw[i] = (1.0f - ALPHA) * r * r;
    }
}

// ---------------- launch 4: CSR edge placement ----------------
__global__ void edge_place(const int* __restrict__ ei32, const float* __restrict__ dinv,
                           int* __restrict__ cursor, int2* __restrict__ edge)
{
    int e = blockIdx.x * 256 + threadIdx.x;
    if (e < N_EDGES) {
        int is64 = g_is64;
        int s = load_idx(ei32, e, is64);
        int d = load_idx(ei32, (long long)N_EDGES + e, is64);
        if ((unsigned)s >= N_NODES) s = 0;
        if ((unsigned)d >= N_NODES) d = 0;
        int pos = atomicAdd(&cursor[d], 1);
        float w = (1.0f - ALPHA) * dinv[s] * dinv[d];
        edge[pos] = make_int2(s, __float_as_int(w));
    }
}

// ---------------- per-hop fused pull: 16 lanes per node, 4 edges/iter ----------------
// out[n] = alpha*h0[n] + selfw[n]*cur[n] + sum_e w_e * cur[src_e]
// edge ranges padded to multiple of 4 with {src=0, w=0}.
template <bool FINAL>
__global__ __launch_bounds__(256) void prop_kernel(
    const __half* __restrict__ cur, const __half* __restrict__ h0,
    const float* __restrict__ selfw,
    const int* __restrict__ rowbeg, const int* __restrict__ cnt,
    const int2* __restrict__ edge, void* __restrict__ outp)
{
    int gtid = blockIdx.x * 256 + threadIdx.x;
    int n = gtid >> 4;          // 16 lanes per node
    int l = gtid & 15;
    if (n >= N_NODES) return;

    const size_t off = (size_t)n * HIDDEN + l * 8;
    float4 h0L, h0H, svL, svH;
    ldh8(h0 + off, h0L, h0H);
    ldh8(cur + off, svL, svH);
    float sw = selfw[n];

    float4 aL, aH;
    aL.x = ALPHA * h0L.x + sw * svL.x;  aL.y = ALPHA * h0L.y + sw * svL.y;
    aL.z = ALPHA * h0L.z + sw * svL.z;  aL.w = ALPHA * h0L.w + sw * svL.w;
    aH.x = ALPHA * h0H.x + sw * svH.x;  aH.y = ALPHA * h0H.y + sw * svH.y;
    aH.z = ALPHA * h0H.z + sw * svH.z;  aH.w = ALPHA * h0H.w + sw * svH.w;

    int beg = __ldg(rowbeg + n);
    int end = beg + ((__ldg(cnt + n) + 3) & ~3);
    for (int j = beg; j < end; j += 4) {
        const int4* ep = (const int4*)(edge + j);   // 4 edges = 2 int4
        int4 E0 = __ldg(ep);
        int4 E1 = __ldg(ep + 1);
        float4 v0L,v0H,v1L,v1H,v2L,v2H,v3L,v3H;
        ldh8(cur + (size_t)E0.x * HIDDEN + l * 8, v0L, v0H);
        ldh8(cur + (size_t)E0.z * HIDDEN + l * 8, v1L, v1H);
        ldh8(cur + (size_t)E1.x * HIDDEN + l * 8, v2L, v2H);
        ldh8(cur + (size_t)E1.z * HIDDEN + l * 8, v3L, v3H);
        fma8(aL, aH, __int_as_float(E0.y), v0L, v0H);
        fma8(aL, aH, __int_as_float(E0.w), v1L, v1H);
        fma8(aL, aH, __int_as_float(E1.y), v2L, v2H);
        fma8(aL, aH, __int_as_float(E1.w), v3L, v3H);
    }

    if (FINAL) {
        float* o = (float*)outp + off;
        *(float4*)o       = aL;
        *(float4*)(o + 4) = aH;
    } else {
        __half* o = (__half*)outp + off;
        sth4(o, aL);
        sth4(o + 4, aH);
    }
}

// ---------------- launch ----------------
extern "C" void kernel_launch(void* const* d_in, const int* in_sizes, int n_in,
                              void* d_out, int out_size)
{
    const float* x    = (const float*)d_in[0];
    const int*   ei32 = (const int*)d_in[1];    // int32 OR int64 (device probe)
    const float* W    = (const float*)d_in[2];
    const float* b    = (const float*)d_in[3];
    float* out = (float*)d_out;

    __half *Wh, *h0h, *bufA, *bufB;
    float *dinv, *selfw;
    int *cnt, *rowbeg, *cursor;
    int2 *edge;
    cudaGetSymbolAddress((void**)&Wh,      g_Wh);
    cudaGetSymbolAddress((void**)&h0h,     g_h0h);
    cudaGetSymbolAddress((void**)&bufA,    g_bufA);
    cudaGetSymbolAddress((void**)&bufB,    g_bufB);
    cudaGetSymbolAddress((void**)&cnt,     g_cnt);
    cudaGetSymbolAddress((void**)&rowbeg,  g_rowbeg);
    cudaGetSymbolAddress((void**)&cursor,  g_cursor);
    cudaGetSymbolAddress((void**)&dinv,    g_dinv);
    cudaGetSymbolAddress((void**)&selfw,   g_selfw);
    cudaGetSymbolAddress((void**)&edge,    g_edge);

    const int NB_N = (N_NODES + 255) / 256;   // 391
    const int NB_E = (N_EDGES + 255) / 256;   // 2344
    const int NB_G = (N_NODES + 127) / 128;   // 782

    probe_zero<<<NB_N, 256>>>(ei32, W, cnt, edge, Wh);            // 0
    deg_count <<<NB_E, 256>>>(ei32, cnt);                         // 1
    gemm_hmma <<<NB_G, 256>>>(x, Wh, b, h0h);                     // 2
    alloc_prep<<<NB_N, 256>>>(cnt, rowbeg, cursor, dinv, selfw);  // 3
    edge_place<<<NB_E, 256>>>(ei32, dinv, cursor, edge);          // 4

    const int NB_PROP = (N_NODES * 16 + 255) / 256;   // 6250
    const __half* cur = h0h;
    for (int hop = 0; hop < KHOPS; hop++) {           // first prop = index 5
        if (hop == KHOPS - 1) {
            prop_kernel<true><<<NB_PROP, 256>>>(cur, h0h, selfw, rowbeg, cnt, edge, out);
        } else {
            __half* nxt = (hop & 1) ? bufB : bufA;
            prop_kernel<false><<<NB_PROP, 256>>>(cur, h0h, selfw, rowbeg, cnt, edge, nxt);
            cur = nxt;
        }
    }
}

// round 8
// speedup vs baseline: 1.8592x; 1.0475x over previous
#include <cuda_runtime.h>
#include <cuda_fp16.h>
#include <cstdint>

#define N_NODES 100000
#define N_EDGES 600000
#define HIDDEN  128
#define ALPHA   0.1f
#define KHOPS   10
#define EDGE_CAP 1000000   // 600k edges + <=3 pad per node
#define NBLK_N  391        // ceil(N_NODES/256)

// ---------------- device scratch (static; no allocation) ----------------
__device__ __half g_Wh  [HIDDEN * HIDDEN];
__device__ __half g_h0h [(size_t)N_NODES * HIDDEN];
__device__ __half g_bufA[(size_t)N_NODES * HIDDEN];
__device__ __half g_bufB[(size_t)N_NODES * HIDDEN];
__device__ int    g_cnt     [N_NODES];
__device__ int    g_rowloc  [N_NODES];      // exclusive prefix within block
__device__ int    g_blocksum[NBLK_N];
__device__ int    g_blockoff[NBLK_N];
__device__ int    g_rowptr  [N_NODES + 1];
__device__ int    g_cursor  [N_NODES];
__device__ float  g_dinv    [N_NODES];
__device__ float  g_selfw   [N_NODES];      // (1-alpha) * dinv^2
__device__ int2   g_edge    [EDGE_CAP];     // CSR by dst: {src, weight bits}
__device__ int    g_is64;

// ---------------- fp16 vector helpers ----------------
__device__ __forceinline__ void sth4(__half* p, float4 v) {
    __half2 a = __floats2half2_rn(v.x, v.y);
    __half2 b = __floats2half2_rn(v.z, v.w);
    uint2 raw;
    raw.x = *(unsigned*)&a;
    raw.y = *(unsigned*)&b;
    *(uint2*)p = raw;
}
__device__ __forceinline__ void ldh8(const __half* p, float4& lo, float4& hi) {
    uint4 raw = *(const uint4*)p;
    float2 f0 = __half22float2(*(__half2*)&raw.x);
    float2 f1 = __half22float2(*(__half2*)&raw.y);
    float2 f2 = __half22float2(*(__half2*)&raw.z);
    float2 f3 = __half22float2(*(__half2*)&raw.w);
    lo = make_float4(f0.x, f0.y, f1.x, f1.y);
    hi = make_float4(f2.x, f2.y, f3.x, f3.y);
}
__device__ __forceinline__ void fma8(float4& aL, float4& aH, float w, float4 vL, float4 vH) {
    aL.x += w * vL.x; aL.y += w * vL.y; aL.z += w * vL.z; aL.w += w * vL.w;
    aH.x += w * vH.x; aH.y += w * vH.y; aH.z += w * vH.z; aH.w += w * vH.w;
}
__device__ __forceinline__ unsigned f2h2(float a, float b) {
    __half2 h = __floats2half2_rn(a, b);
    return *(unsigned*)&h;
}

// ---------------- launch 0: zero cnt + convert W + probe ----------------
__global__ void probe_zero(const int* __restrict__ ei32, const float* __restrict__ W,
                           int* __restrict__ cnt, __half* __restrict__ Wh) {
    int i = blockIdx.x * 256 + threadIdx.x;
    if (i < N_NODES) cnt[i] = 0;
    if (i < HIDDEN * HIDDEN / 4) {
        float4 v = ((const float4*)W)[i];
        sth4(Wh + (size_t)i * 4, v);
    }
    if (i == 0) {
        int acc = 0;
        for (int k = 0; k < 128; k++) acc |= ei32[2 * k + 1];
        g_is64 = (acc == 0) ? 1 : 0;
    }
}

__device__ __forceinline__ int load_idx(const int* ei32, long long pos, int is64) {
    return is64 ? ei32[2 * pos] : ei32[pos];
}

// ---------------- launch 1: in-degree count ----------------
__global__ void deg_count(const int* __restrict__ ei32, int* __restrict__ cnt) {
    int e = blockIdx.x * 256 + threadIdx.x;
    if (e < N_EDGES) {
        int d = load_idx(ei32, (long long)N_EDGES + e, g_is64);
        if ((unsigned)d < N_NODES) atomicAdd(&cnt[d], 1);
    }
}

// ---------------- launch 2: per-block exclusive scan of padded counts ----------------
__global__ __launch_bounds__(256) void scan_block(
    const int* __restrict__ cnt, int* __restrict__ rowloc, int* __restrict__ blocksum)
{
    __shared__ int sh[256];
    int t = threadIdx.x;
    int i = blockIdx.x * 256 + t;
    int c = (i < N_NODES) ? ((cnt[i] + 3) & ~3) : 0;
    sh[t] = c;
    __syncthreads();
    for (int d = 1; d < 256; d <<= 1) {
        int v = (t >= d) ? sh[t - d] : 0;
        __syncthreads();
        sh[t] += v;
        __syncthreads();
    }
    if (i < N_NODES) rowloc[i] = sh[t] - c;
    if (t == 255) blocksum[blockIdx.x] = sh[255];
}

// ---------------- launch 3: tensor-core GEMM h0 = x @ W^T + b (profiled) ----------------
#define WSTRIDE 136
__global__ __launch_bounds__(256) void gemm_hmma(
    const float* __restrict__ x, const __half* __restrict__ Wh,
    const float* __restrict__ b, __half* __restrict__ out)
{
    __shared__ __half Ws[128 * WSTRIDE];
    __shared__ float bs[128];
    const int tid = threadIdx.x;

#pragma unroll
    for (int it = 0; it < 8; it++) {
        int idx = it * 256 + tid;
        int r = idx >> 4, c = (idx & 15) * 8;
        *(uint4*)&Ws[r * WSTRIDE + c] = ((const uint4*)Wh)[idx];
    }
    if (tid < 128) bs[tid] = b[tid];
    __syncthreads();

    const int w = tid >> 5, lane = tid & 31;
    const int r  = lane >> 2;
    const int kq = (lane & 3) * 2;
    const int Rbase = blockIdx.x * 128 + w * 16;

    int row0 = Rbase + r;
    int row1 = Rbase + r + 8;
    int row0c = row0 < N_NODES ? row0 : 0;
    int row1c = row1 < N_NODES ? row1 : 0;

    float d[16][4];
#pragma unroll
    for (int nt = 0; nt < 16; nt++)
#pragma unroll
        for (int q = 0; q < 4; q++) d[nt][q] = 0.0f;

    const float* a0p = x + (size_t)row0c * HIDDEN;
    const float* a1p = x + (size_t)row1c * HIDDEN;

    // software-pipelined A loads: fetch k-step ks+1 while doing MMAs of ks
    float2 f0 = *(const float2*)(a0p + kq);
    float2 f1 = *(const float2*)(a1p + kq);
    float2 f2 = *(const float2*)(a0p + kq + 8);
    float2 f3 = *(const float2*)(a1p + kq + 8);

#pragma unroll
    for (int ks = 0; ks < 8; ks++) {
        unsigned a0 = f2h2(f0.x, f0.y);
        unsigned a1 = f2h2(f1.x, f1.y);
        unsigned a2 = f2h2(f2.x, f2.y);
        unsigned a3 = f2h2(f3.x, f3.y);
        if (ks < 7) {
            int k0 = (ks + 1) * 16 + kq;
            f0 = *(const float2*)(a0p + k0);
            f1 = *(const float2*)(a1p + k0);
            f2 = *(const float2*)(a0p + k0 + 8);
            f3 = *(const float2*)(a1p + k0 + 8);
        }
#pragma unroll
        for (int nt = 0; nt < 16; nt++) {
            int c = nt * 8 + r;
            unsigned b0 = *(const unsigned*)&Ws[c * WSTRIDE + ks * 16 + kq];
            unsigned b1 = *(const unsigned*)&Ws[c * WSTRIDE + ks * 16 + kq + 8];
            asm volatile(
                "mma.sync.aligned.m16n8k16.row.col.f32.f16.f16.f32 "
                "{%0,%1,%2,%3}, {%4,%5,%6,%7}, {%8,%9}, {%0,%1,%2,%3};"
                : "+f"(d[nt][0]), "+f"(d[nt][1]), "+f"(d[nt][2]), "+f"(d[nt][3])
                : "r"(a0), "r"(a1), "r"(a2), "r"(a3), "r"(b0), "r"(b1));
        }
    }

    const int c0 = (lane & 3) * 2;
#pragma unroll
    for (int nt = 0; nt < 16; nt++) {
        int col = nt * 8 + c0;
        if (row0 < N_NODES) {
            __half2 v = __floats2half2_rn(d[nt][0] + bs[col], d[nt][1] + bs[col + 1]);
            *(__half2*)&out[(size_t)row0 * HIDDEN + col] = v;
        }
        if (row1 < N_NODES) {
            __half2 v = __floats2half2_rn(d[nt][2] + bs[col], d[nt][3] + bs[col + 1]);
            *(__half2*)&out[(size_t)row1 * HIDDEN + col] = v;
        }
    }
}

// ---------------- launch 4: scan of 391 block sums ----------------
__global__ __launch_bounds__(512) void scan_top(
    const int* __restrict__ blocksum, int* __restrict__ blockoff)
{
    __shared__ int sh[512];
    int t = threadIdx.x;
    int v = (t < NBLK_N) ? blocksum[t] : 0;
    sh[t] = v;
    __syncthreads();
    for (int d = 1; d < 512; d <<= 1) {
        int u = (t >= d) ? sh[t - d] : 0;
        __syncthreads();
        sh[t] += u;
        __syncthreads();
    }
    if (t < NBLK_N) blockoff[t] = sh[t] - v;
}

// ---------------- launch 5: apply offsets + node prep + write pad slots ----------------
__global__ void prep_apply(const int* __restrict__ cnt, const int* __restrict__ rowloc,
                           const int* __restrict__ blockoff,
                           int* __restrict__ row_ptr, int* __restrict__ cursor,
                           float* __restrict__ dinv, float* __restrict__ selfw,
                           int2* __restrict__ edge)
{
    int i = blockIdx.x * 256 + threadIdx.x;
    if (i < N_NODES) {
        int c = cnt[i];
        int pad = (c + 3) & ~3;
        int beg = rowloc[i] + blockoff[blockIdx.x];
        row_ptr[i] = beg;
        cursor[i]  = beg;
        for (int k = c; k < pad; k++) edge[beg + k] = make_int2(0, 0);
        float r = rsqrtf((float)c + 1.0f);
        dinv[i]  = r;
        selfw[i] = (1.0f - ALPHA) * r * r;
        if (i == N_NODES - 1) row_ptr[N_NODES] = beg + pad;
    }
}

// ---------------- launch 6: CSR edge placement ----------------
__global__ void edge_place(const int* __restrict__ ei32, const float* __restrict__ dinv,
                           int* __restrict__ cursor, int2* __restrict__ edge)
{
    int e = blockIdx.x * 256 + threadIdx.x;
    if (e < N_EDGES) {
        int is64 = g_is64;
        int s = load_idx(ei32, e, is64);
        int d = load_idx(ei32, (long long)N_EDGES + e, is64);
        if ((unsigned)s >= N_NODES) s = 0;
        if ((unsigned)d >= N_NODES) d = 0;
        int pos = atomicAdd(&cursor[d], 1);
        float w = (1.0f - ALPHA) * dinv[s] * dinv[d];
        edge[pos] = make_int2(s, __float_as_int(w));
    }
}

// ---------------- per-hop fused pull: 16 lanes per node, 4 edges/iter ----------------
template <bool FINAL>
__global__ __launch_bounds__(256) void prop_kernel(
    const __half* __restrict__ cur, const __half* __restrict__ h0,
    const float* __restrict__ selfw,
    const int* __restrict__ row_ptr, const int2* __restrict__ edge,
    void* __restrict__ outp)
{
    int gtid = blockIdx.x * 256 + threadIdx.x;
    int n = gtid >> 4;
    int l = gtid & 15;
    if (n >= N_NODES) return;

    const size_t off = (size_t)n * HIDDEN + l * 8;
    float4 h0L, h0H, svL, svH;
    ldh8(h0 + off, h0L, h0H);
    ldh8(cur + off, svL, svH);
    float sw = selfw[n];

    float4 aL, aH;
    aL.x = ALPHA * h0L.x + sw * svL.x;  aL.y = ALPHA * h0L.y + sw * svL.y;
    aL.z = ALPHA * h0L.z + sw * svL.z;  aL.w = ALPHA * h0L.w + sw * svL.w;
    aH.x = ALPHA * h0H.x + sw * svH.x;  aH.y = ALPHA * h0H.y + sw * svH.y;
    aH.z = ALPHA * h0H.z + sw * svH.z;  aH.w = ALPHA * h0H.w + sw * svH.w;

    int beg = __ldg(row_ptr + n);
    int end = __ldg(row_ptr + n + 1);
    for (int j = beg; j < end; j += 4) {
        const int4* ep = (const int4*)(edge + j);
        int4 E0 = __ldg(ep);
        int4 E1 = __ldg(ep + 1);
        float4 v0L,v0H,v1L,v1H,v2L,v2H,v3L,v3H;
        ldh8(cur + (size_t)E0.x * HIDDEN + l * 8, v0L, v0H);
        ldh8(cur + (size_t)E0.z * HIDDEN + l * 8, v1L, v1H);
        ldh8(cur + (size_t)E1.x * HIDDEN + l * 8, v2L, v2H);
        ldh8(cur + (size_t)E1.z * HIDDEN + l * 8, v3L, v3H);
        fma8(aL, aH, __int_as_float(E0.y), v0L, v0H);
        fma8(aL, aH, __int_as_float(E0.w), v1L, v1H);
        fma8(aL, aH, __int_as_float(E1.y), v2L, v2H);
        fma8(aL, aH, __int_as_float(E1.w), v3L, v3H);
    }

    if (FINAL) {
        float* o = (float*)outp + off;
        *(float4*)o       = aL;
        *(float4*)(o + 4) = aH;
    } else {
        __half* o = (__half*)outp + off;
        sth4(o, aL);
        sth4(o + 4, aH);
    }
}

// ---------------- launch ----------------
extern "C" void kernel_launch(void* const* d_in, const int* in_sizes, int n_in,
                              void* d_out, int out_size)
{
    const float* x    = (const float*)d_in[0];
    const int*   ei32 = (const int*)d_in[1];
    const float* W    = (const float*)d_in[2];
    const float* b    = (const float*)d_in[3];
    float* out = (float*)d_out;

    __half *Wh, *h0h, *bufA, *bufB;
    float *dinv, *selfw;
    int *cnt, *rowloc, *blocksum, *blockoff, *row_ptr, *cursor;
    int2 *edge;
    cudaGetSymbolAddress((void**)&Wh,       g_Wh);
    cudaGetSymbolAddress((void**)&h0h,      g_h0h);
    cudaGetSymbolAddress((void**)&bufA,     g_bufA);
    cudaGetSymbolAddress((void**)&bufB,     g_bufB);
    cudaGetSymbolAddress((void**)&cnt,      g_cnt);
    cudaGetSymbolAddress((void**)&rowloc,   g_rowloc);
    cudaGetSymbolAddress((void**)&blocksum, g_blocksum);
    cudaGetSymbolAddress((void**)&blockoff, g_blockoff);
    cudaGetSymbolAddress((void**)&row_ptr,  g_rowptr);
    cudaGetSymbolAddress((void**)&cursor,   g_cursor);
    cudaGetSymbolAddress((void**)&dinv,     g_dinv);
    cudaGetSymbolAddress((void**)&selfw,    g_selfw);
    cudaGetSymbolAddress((void**)&edge,     g_edge);

    const int NB_E = (N_EDGES + 255) / 256;   // 2344
    const int NB_G = (N_NODES + 127) / 128;   // 782

    probe_zero<<<NBLK_N, 256>>>(ei32, W, cnt, Wh);                         // 0
    deg_count <<<NB_E, 256>>>(ei32, cnt);                                  // 1
    scan_block<<<NBLK_N, 256>>>(cnt, rowloc, blocksum);                    // 2
    gemm_hmma <<<NB_G, 256>>>(x, Wh, b, h0h);                              // 3 (profiled)
    scan_top  <<<1, 512>>>(blocksum, blockoff);                            // 4
    prep_apply<<<NBLK_N, 256>>>(cnt, rowloc, blockoff, row_ptr, cursor,
                                dinv, selfw, edge);                        // 5
    edge_place<<<NB_E, 256>>>(ei32, dinv, cursor, edge);                   // 6

    const int NB_PROP = (N_NODES * 16 + 255) / 256;   // 6250
    const __half* cur = h0h;
    for (int hop = 0; hop < KHOPS; hop++) {
        if (hop == KHOPS - 1) {
            prop_kernel<true><<<NB_PROP, 256>>>(cur, h0h, selfw, row_ptr, edge, out);
        } else {
            __half* nxt = (hop & 1) ? bufB : bufA;
            prop_kernel<false><<<NB_PROP, 256>>>(cur, h0h, selfw, row_ptr, edge, nxt);
            cur = nxt;
        }
    }
}